// round 5
// baseline (speedup 1.0000x reference)
#include <cuda_runtime.h>
#include <math.h>
#include <stdint.h>

#define N_PTS 2000000
#define N_CLU 65536
#define CHUNK 32
#define N_CHUNKS (N_PTS / CHUNK)   // 62500 exactly

__device__ float g_agg[N_CLU * 64];
__device__ float g_mid[N_CLU * 128];   // blocked: [c/32][k][c%32]
__device__ int   g_cnt[N_CLU];
__device__ int   g_cur[N_CLU];
__device__ int   g_sidx[N_PTS];
__device__ int   g_slbl[N_PTS];

// ---------------------------------------------------------------------------
__device__ __forceinline__ uint64_t pack2(float lo, float hi) {
    uint64_t r; asm("mov.b64 %0,{%1,%2};" : "=l"(r) : "f"(lo), "f"(hi)); return r;
}
__device__ __forceinline__ float2 unpack2(uint64_t v) {
    float2 r; asm("mov.b64 {%0,%1},%2;" : "=f"(r.x), "=f"(r.y) : "l"(v)); return r;
}
__device__ __forceinline__ uint64_t fma2(uint64_t a, uint64_t b, uint64_t c) {
    uint64_t d; asm("fma.rn.f32x2 %0,%1,%2,%3;" : "=l"(d) : "l"(a), "l"(b), "l"(c)); return d;
}
__device__ __forceinline__ uint64_t relu2(uint64_t v) {
    float2 f = unpack2(v);
    return pack2(fmaxf(f.x, 0.0f), fmaxf(f.y, 0.0f));
}
__device__ __forceinline__ void red4(float* p, float a, float b, float c, float d) {
    asm volatile("red.global.add.v4.f32 [%0], {%1,%2,%3,%4};"
                 :: "l"(p), "f"(a), "f"(b), "f"(c), "f"(d) : "memory");
}

// ---------------------------------------------------------------------------
// zeroing
// ---------------------------------------------------------------------------
__global__ void k_zero_agg() {
    int i = blockIdx.x * 256 + threadIdx.x;
    ((float4*)g_agg)[i] = make_float4(0.f, 0.f, 0.f, 0.f);
}
__global__ void k_zero_cnt() {
    int i = blockIdx.x * 256 + threadIdx.x;
    ((int4*)g_cnt)[i] = make_int4(0, 0, 0, 0);
}

// ---------------------------------------------------------------------------
// counting sort: histogram -> scan -> scatter
// ---------------------------------------------------------------------------
__global__ void k_hist(const int* __restrict__ labels) {
    int i = blockIdx.x * 256 + threadIdx.x;
    if (i < N_PTS) atomicAdd(&g_cnt[labels[i]], 1);
}

__global__ __launch_bounds__(1024) void k_scan() {
    __shared__ int sp[1024];
    const int t = threadIdx.x;
    const int base = t * 64;
    int sum = 0;
#pragma unroll 8
    for (int k = 0; k < 64; k++) sum += g_cnt[base + k];
    sp[t] = sum;
    __syncthreads();
    for (int o = 1; o < 1024; o <<= 1) {
        int add = (t >= o) ? sp[t - o] : 0;
        __syncthreads();
        sp[t] += add;
        __syncthreads();
    }
    int run = sp[t] - sum;   // exclusive prefix for this thread's range
#pragma unroll 8
    for (int k = 0; k < 64; k++) {
        g_cur[base + k] = run;
        run += g_cnt[base + k];
    }
}

__global__ void k_scatter(const int* __restrict__ labels) {
    int i = blockIdx.x * 256 + threadIdx.x;
    if (i < N_PTS) {
        int l = labels[i];
        int pos = atomicAdd(&g_cur[l], 1);
        g_sidx[pos] = i;
        g_slbl[pos] = l;
    }
}

// ---------------------------------------------------------------------------
// k_point: sorted walk, register accumulation, flush on label change.
// j-pair f32x2 packing: activation duplicated, weights natural pairs.
// ---------------------------------------------------------------------------
__global__ __launch_bounds__(128) void k_point(
    const float* __restrict__ pf,
    const float* __restrict__ cc, const float* __restrict__ pts,
    const float* __restrict__ we0, const float* __restrict__ be0,
    const float* __restrict__ we1, const float* __restrict__ be1,
    const float* __restrict__ we2, const float* __restrict__ be2,
    const float* __restrict__ we3, const float* __restrict__ be3,
    const float* __restrict__ wa0, const float* __restrict__ ba0,
    const float* __restrict__ wa1, const float* __restrict__ ba1)
{
    __shared__ __align__(16) float s[3729];
    float* sWE0 = s + 0;     // 88
    float* sBE0 = s + 88;    // 8
    float* sWE1 = s + 96;    // 128
    float* sBE1 = s + 224;   // 16
    float* sWE2 = s + 240;   // 512
    float* sBE2 = s + 752;   // 32
    float* sWE3 = s + 784;   // 2048
    float* sBE3 = s + 2832;  // 64
    float* sWA0 = s + 2896;  // 704
    float* sBA0 = s + 3600;  // 64
    float* sWA1 = s + 3664;  // 64
    float* sBA1 = s + 3728;  // 1

    const int t = threadIdx.x;
    #define CPY(dst, src, n) for (int i = t; i < (n); i += 128) (dst)[i] = (src)[i];
    CPY(sWE0, we0, 88)   CPY(sBE0, be0, 8)
    CPY(sWE1, we1, 128)  CPY(sBE1, be1, 16)
    CPY(sWE2, we2, 512)  CPY(sBE2, be2, 32)
    CPY(sWE3, we3, 2048) CPY(sBE3, be3, 64)
    CPY(sWA0, wa0, 704)  CPY(sBA0, ba0, 64)
    CPY(sWA1, wa1, 64)   if (t == 0) sBA1[0] = ba1[0];
    #undef CPY
    __syncthreads();

    const int gid = blockIdx.x * 128 + t;
    if (gid >= N_CHUNKS) return;
    const int start = gid * CHUNK;
    const float ba1s = sBA1[0];

    uint64_t acc[32];
#pragma unroll
    for (int m = 0; m < 32; m++) acc[m] = 0ULL;

    int cur = g_slbl[start];

#pragma unroll 1
    for (int p = 0; p < CHUNK; p++) {
        const int sp_ = start + p;
        const int lbl = g_slbl[sp_];
        if (lbl != cur) {
            float* dst = g_agg + (size_t)cur * 64;
#pragma unroll
            for (int m4 = 0; m4 < 16; m4++) {
                float2 f0 = unpack2(acc[2 * m4]);
                float2 f1 = unpack2(acc[2 * m4 + 1]);
                red4(dst + m4 * 4, f0.x, f0.y, f1.x, f1.y);
                acc[2 * m4] = 0ULL; acc[2 * m4 + 1] = 0ULL;
            }
            cur = lbl;
        }
        const int i = g_sidx[sp_];

        // build duplicated input
        uint64_t xd[11];
        {
            const float4* p4 = (const float4*)(pf + (size_t)i * 8);
            float4 v0 = p4[0], v1 = p4[1];
            xd[0] = pack2(v0.x, v0.x); xd[1] = pack2(v0.y, v0.y);
            xd[2] = pack2(v0.z, v0.z); xd[3] = pack2(v0.w, v0.w);
            xd[4] = pack2(v1.x, v1.x); xd[5] = pack2(v1.y, v1.y);
            xd[6] = pack2(v1.z, v1.z); xd[7] = pack2(v1.w, v1.w);
#pragma unroll
            for (int k = 0; k < 3; k++) {
                float d = cc[(size_t)lbl * 3 + k] - pts[(size_t)i * 3 + k];
                xd[8 + k] = pack2(d, d);
            }
        }

        // ----- attention -----
        uint64_t aa = 0ULL;
#pragma unroll
        for (int j4 = 0; j4 < 64; j4 += 4) {
            ulonglong2 b = *(const ulonglong2*)&sBA0[j4];
            uint64_t c0 = b.x, c1 = b.y;
#pragma unroll
            for (int k = 0; k < 11; k++) {
                ulonglong2 w = *(const ulonglong2*)&sWA0[k * 64 + j4];
                c0 = fma2(xd[k], w.x, c0);
                c1 = fma2(xd[k], w.y, c1);
            }
            ulonglong2 w1 = *(const ulonglong2*)&sWA1[j4];
            aa = fma2(relu2(c0), w1.x, aa);
            aa = fma2(relu2(c1), w1.y, aa);
        }
        uint64_t ad;
        {
            float2 f = unpack2(aa);
            float a = 1.0f / (1.0f + __expf(-(f.x + f.y + ba1s)));
            ad = pack2(a, a);
        }

        // ----- edge L0: 11 -> 8 -----
        uint64_t h0d[8];
#pragma unroll
        for (int j4 = 0; j4 < 8; j4 += 4) {
            ulonglong2 b = *(const ulonglong2*)&sBE0[j4];
            uint64_t c0 = b.x, c1 = b.y;
#pragma unroll
            for (int k = 0; k < 11; k++) {
                ulonglong2 w = *(const ulonglong2*)&sWE0[k * 8 + j4];
                c0 = fma2(xd[k], w.x, c0);
                c1 = fma2(xd[k], w.y, c1);
            }
            float2 f0 = unpack2(c0), f1 = unpack2(c1);
            float v0 = fmaxf(f0.x, 0.f), v1 = fmaxf(f0.y, 0.f);
            float v2 = fmaxf(f1.x, 0.f), v3 = fmaxf(f1.y, 0.f);
            h0d[j4] = pack2(v0, v0); h0d[j4 + 1] = pack2(v1, v1);
            h0d[j4 + 2] = pack2(v2, v2); h0d[j4 + 3] = pack2(v3, v3);
        }

        // ----- edge L1: 8 -> 16 -----
        uint64_t h1d[16];
#pragma unroll
        for (int j4 = 0; j4 < 16; j4 += 4) {
            ulonglong2 b = *(const ulonglong2*)&sBE1[j4];
            uint64_t c0 = b.x, c1 = b.y;
#pragma unroll
            for (int k = 0; k < 8; k++) {
                ulonglong2 w = *(const ulonglong2*)&sWE1[k * 16 + j4];
                c0 = fma2(h0d[k], w.x, c0);
                c1 = fma2(h0d[k], w.y, c1);
            }
            float2 f0 = unpack2(c0), f1 = unpack2(c1);
            float v0 = fmaxf(f0.x, 0.f), v1 = fmaxf(f0.y, 0.f);
            float v2 = fmaxf(f1.x, 0.f), v3 = fmaxf(f1.y, 0.f);
            h1d[j4] = pack2(v0, v0); h1d[j4 + 1] = pack2(v1, v1);
            h1d[j4 + 2] = pack2(v2, v2); h1d[j4 + 3] = pack2(v3, v3);
        }

        // ----- edge L2: 16 -> 32 -----
        uint64_t h2d[32];
#pragma unroll
        for (int j4 = 0; j4 < 32; j4 += 4) {
            ulonglong2 b = *(const ulonglong2*)&sBE2[j4];
            uint64_t c0 = b.x, c1 = b.y;
#pragma unroll
            for (int k = 0; k < 16; k++) {
                ulonglong2 w = *(const ulonglong2*)&sWE2[k * 32 + j4];
                c0 = fma2(h1d[k], w.x, c0);
                c1 = fma2(h1d[k], w.y, c1);
            }
            float2 f0 = unpack2(c0), f1 = unpack2(c1);
            float v0 = fmaxf(f0.x, 0.f), v1 = fmaxf(f0.y, 0.f);
            float v2 = fmaxf(f1.x, 0.f), v3 = fmaxf(f1.y, 0.f);
            h2d[j4] = pack2(v0, v0); h2d[j4 + 1] = pack2(v1, v1);
            h2d[j4 + 2] = pack2(v2, v2); h2d[j4 + 3] = pack2(v3, v3);
        }

        // ----- edge L3: 32 -> 64, accumulate t = relu(.)*a into acc -----
#pragma unroll
        for (int j4 = 0; j4 < 64; j4 += 4) {
            ulonglong2 b = *(const ulonglong2*)&sBE3[j4];
            uint64_t c0 = b.x, c1 = b.y;
#pragma unroll
            for (int k = 0; k < 32; k++) {
                ulonglong2 w = *(const ulonglong2*)&sWE3[k * 64 + j4];
                c0 = fma2(h2d[k], w.x, c0);
                c1 = fma2(h2d[k], w.y, c1);
            }
            acc[j4 / 2]     = fma2(relu2(c0), ad, acc[j4 / 2]);
            acc[j4 / 2 + 1] = fma2(relu2(c1), ad, acc[j4 / 2 + 1]);
        }
    }

    // final flush
    {
        float* dst = g_agg + (size_t)cur * 64;
#pragma unroll
        for (int m4 = 0; m4 < 16; m4++) {
            float2 f0 = unpack2(acc[2 * m4]);
            float2 f1 = unpack2(acc[2 * m4 + 1]);
            red4(dst + m4 * 4, f0.x, f0.y, f1.x, f1.y);
        }
    }
}

// ---------------------------------------------------------------------------
// Kernel 2: g_mid = relu(g_agg @ wo0 + bo0). 16 clusters/block.
// Output blocked [c/32][k][c%32].
// ---------------------------------------------------------------------------
__global__ __launch_bounds__(256) void k_mid(
    const float* __restrict__ wo0, const float* __restrict__ bo0)
{
    __shared__ float sw[64 * 128];
    __shared__ float sb[128];
    __shared__ __align__(16) float saggT[64 * 16];

    const int t  = threadIdx.x;
    const int cb = blockIdx.x * 16;

    for (int i = t; i < 8192; i += 256) sw[i] = wo0[i];
    if (t < 128) sb[t] = bo0[t];
    {
        int c  = t >> 4;
        int k4 = t & 15;
        float4 v = ((const float4*)g_agg)[(size_t)(cb + c) * 16 + k4];
        saggT[(k4 * 4 + 0) * 16 + c] = v.x;
        saggT[(k4 * 4 + 1) * 16 + c] = v.y;
        saggT[(k4 * 4 + 2) * 16 + c] = v.z;
        saggT[(k4 * 4 + 3) * 16 + c] = v.w;
    }
    __syncthreads();

    const int j    = t & 127;
    const int half = t >> 7;

    uint64_t acc[4];
    {
        float b = sb[j];
#pragma unroll
        for (int p = 0; p < 4; p++) acc[p] = pack2(b, b);
    }

#pragma unroll 4
    for (int k = 0; k < 64; k++) {
        float w = sw[k * 128 + j];
        uint64_t w2 = pack2(w, w);
        const uint64_t* row = (const uint64_t*)(saggT + k * 16) + half * 4;
        ulonglong2 m0 = *(const ulonglong2*)(row);
        ulonglong2 m1 = *(const ulonglong2*)(row + 2);
        acc[0] = fma2(m0.x, w2, acc[0]);
        acc[1] = fma2(m0.y, w2, acc[1]);
        acc[2] = fma2(m1.x, w2, acc[2]);
        acc[3] = fma2(m1.y, w2, acc[3]);
    }

    const int group = blockIdx.x >> 1;
    const int lane0 = (blockIdx.x & 1) * 16 + half * 8;
    float* dst = g_mid + (size_t)group * 4096 + (size_t)j * 32 + lane0;
#pragma unroll
    for (int p = 0; p < 4; p++) {
        float2 f = unpack2(acc[p]);
        f.x = fmaxf(f.x, 0.0f); f.y = fmaxf(f.y, 0.0f);
        ((float2*)dst)[p] = f;
    }
}

// ---------------------------------------------------------------------------
// Kernel 3: out = relu(g_mid @ wo1 + bo1). 32 clusters/block, 128 threads.
// ---------------------------------------------------------------------------
__global__ __launch_bounds__(128) void k_out(
    const float* __restrict__ wo1, const float* __restrict__ bo1,
    float* __restrict__ out)
{
    __shared__ __align__(16) uint64_t smid[128 * 16];

    const int t    = threadIdx.x;
    const int cg   = t & 63;
    const int half = t >> 6;
    const int grp  = blockIdx.x;

    const uint64_t* gm = (const uint64_t*)(g_mid + (size_t)grp * 4096);
    for (int i = t; i < 2048; i += 128) smid[i] = gm[i];
    __syncthreads();

    uint64_t acc[4][8];
    {
        float4 b = ((const float4*)bo1)[cg];
#pragma unroll
        for (int p = 0; p < 8; p++) {
            acc[0][p] = pack2(b.x, b.x); acc[1][p] = pack2(b.y, b.y);
            acc[2][p] = pack2(b.z, b.z); acc[3][p] = pack2(b.w, b.w);
        }
    }

    const float4* w4p = (const float4*)wo1;
#pragma unroll 4
    for (int k = 0; k < 128; k++) {
        float4 w = w4p[k * 64 + cg];
        uint64_t wd0 = pack2(w.x, w.x), wd1 = pack2(w.y, w.y);
        uint64_t wd2 = pack2(w.z, w.z), wd3 = pack2(w.w, w.w);
        const uint64_t* mrow = smid + k * 16 + half * 8;
        ulonglong2 m0 = *(const ulonglong2*)(mrow);
        ulonglong2 m1 = *(const ulonglong2*)(mrow + 2);
        ulonglong2 m2 = *(const ulonglong2*)(mrow + 4);
        ulonglong2 m3 = *(const ulonglong2*)(mrow + 6);
        uint64_t m[8] = {m0.x, m0.y, m1.x, m1.y, m2.x, m2.y, m3.x, m3.y};
#pragma unroll
        for (int p = 0; p < 8; p++) {
            acc[0][p] = fma2(m[p], wd0, acc[0][p]);
            acc[1][p] = fma2(m[p], wd1, acc[1][p]);
            acc[2][p] = fma2(m[p], wd2, acc[2][p]);
            acc[3][p] = fma2(m[p], wd3, acc[3][p]);
        }
    }

#pragma unroll
    for (int p = 0; p < 8; p++) {
        int pp = half * 8 + p;
        int c0 = grp * 32 + 2 * pp;
        float2 f0 = unpack2(acc[0][p]), f1 = unpack2(acc[1][p]);
        float2 f2 = unpack2(acc[2][p]), f3 = unpack2(acc[3][p]);
        float4 o0 = make_float4(fmaxf(f0.x, 0.f), fmaxf(f1.x, 0.f),
                                fmaxf(f2.x, 0.f), fmaxf(f3.x, 0.f));
        float4 o1 = make_float4(fmaxf(f0.y, 0.f), fmaxf(f1.y, 0.f),
                                fmaxf(f2.y, 0.f), fmaxf(f3.y, 0.f));
        *(float4*)(out + (size_t)c0 * 256 + 4 * cg)       = o0;
        *(float4*)(out + (size_t)(c0 + 1) * 256 + 4 * cg) = o1;
    }
}

// ---------------------------------------------------------------------------
extern "C" void kernel_launch(void* const* d_in, const int* in_sizes, int n_in,
                              void* d_out, int out_size)
{
    const float* pf     = (const float*)d_in[0];
    const int*   labels = (const int*)  d_in[1];
    const float* cc     = (const float*)d_in[2];
    const float* pts    = (const float*)d_in[3];
    const float* we0    = (const float*)d_in[4];
    const float* be0    = (const float*)d_in[5];
    const float* we1    = (const float*)d_in[6];
    const float* be1    = (const float*)d_in[7];
    const float* we2    = (const float*)d_in[8];
    const float* be2    = (const float*)d_in[9];
    const float* we3    = (const float*)d_in[10];
    const float* be3    = (const float*)d_in[11];
    const float* wa0    = (const float*)d_in[12];
    const float* ba0    = (const float*)d_in[13];
    const float* wa1    = (const float*)d_in[14];
    const float* ba1    = (const float*)d_in[15];
    const float* wo0    = (const float*)d_in[16];
    const float* bo0    = (const float*)d_in[17];
    const float* wo1    = (const float*)d_in[18];
    const float* bo1    = (const float*)d_in[19];
    float* out = (float*)d_out;

    k_zero_agg<<<N_CLU * 64 / 4 / 256, 256>>>();
    k_zero_cnt<<<N_CLU / 4 / 256, 256>>>();
    k_hist<<<(N_PTS + 255) / 256, 256>>>(labels);
    k_scan<<<1, 1024>>>();
    k_scatter<<<(N_PTS + 255) / 256, 256>>>(labels);
    k_point<<<(N_CHUNKS + 127) / 128, 128>>>(pf, cc, pts,
                                             we0, be0, we1, be1, we2, be2, we3, be3,
                                             wa0, ba0, wa1, ba1);
    k_mid<<<N_CLU / 16, 256>>>(wo0, bo0);
    k_out<<<N_CLU / 32, 128>>>(wo1, bo1, out);
}

// round 6
// speedup vs baseline: 1.5080x; 1.5080x over previous
#include <cuda_runtime.h>
#include <math.h>
#include <stdint.h>

#define N_PTS 2000000
#define N_CLU 65536
#define N_THREADS_PT (N_PTS / 4)   // 500000 threads, 4 consecutive sorted pts each

__device__ float g_agg[N_CLU * 64];
__device__ float g_mid[N_CLU * 128];   // blocked: [c/32][k][c%32]
__device__ int   g_cnt[N_CLU];
__device__ int   g_cur[N_CLU];
__device__ int   g_bsum[64];
__device__ int   g_sidx[N_PTS];
__device__ int   g_slbl[N_PTS];

// ---------------------------------------------------------------------------
__device__ __forceinline__ uint64_t pack2(float lo, float hi) {
    uint64_t r; asm("mov.b64 %0,{%1,%2};" : "=l"(r) : "f"(lo), "f"(hi)); return r;
}
__device__ __forceinline__ float2 unpack2(uint64_t v) {
    float2 r; asm("mov.b64 {%0,%1},%2;" : "=f"(r.x), "=f"(r.y) : "l"(v)); return r;
}
__device__ __forceinline__ uint64_t fma2(uint64_t a, uint64_t b, uint64_t c) {
    uint64_t d; asm("fma.rn.f32x2 %0,%1,%2,%3;" : "=l"(d) : "l"(a), "l"(b), "l"(c)); return d;
}
__device__ __forceinline__ uint64_t mul2(uint64_t a, uint64_t b) {
    uint64_t d; asm("mul.rn.f32x2 %0,%1,%2;" : "=l"(d) : "l"(a), "l"(b)); return d;
}
__device__ __forceinline__ uint64_t relu2(uint64_t v) {
    float2 f = unpack2(v);
    return pack2(fmaxf(f.x, 0.0f), fmaxf(f.y, 0.0f));
}
__device__ __forceinline__ void red4(float* p, float a, float b, float c, float d) {
    asm volatile("red.global.add.v4.f32 [%0], {%1,%2,%3,%4};"
                 :: "l"(p), "f"(a), "f"(b), "f"(c), "f"(d) : "memory");
}

// ---------------------------------------------------------------------------
// zero + counting sort
// ---------------------------------------------------------------------------
__global__ void k_zero_agg() {
    int i = blockIdx.x * 256 + threadIdx.x;
    ((float4*)g_agg)[i] = make_float4(0.f, 0.f, 0.f, 0.f);
}
__global__ void k_zero_cnt() {
    int i = blockIdx.x * 256 + threadIdx.x;
    ((int4*)g_cnt)[i] = make_int4(0, 0, 0, 0);
}
__global__ void k_hist(const int* __restrict__ labels) {
    int i = blockIdx.x * 256 + threadIdx.x;
    if (i < N_PTS) atomicAdd(&g_cnt[labels[i]], 1);
}
// scan phase 1: 64 blocks x 256 threads, 4 clusters/thread; local scan + block sums
__global__ __launch_bounds__(256) void k_scan1() {
    __shared__ int sp[256];
    int t = threadIdx.x, b = blockIdx.x;
    int base = b * 1024 + t * 4;
    int4 c = *(const int4*)(g_cnt + base);
    int sum = c.x + c.y + c.z + c.w;
    sp[t] = sum;
    __syncthreads();
    for (int o = 1; o < 256; o <<= 1) {
        int v = (t >= o) ? sp[t - o] : 0;
        __syncthreads();
        sp[t] += v;
        __syncthreads();
    }
    int excl = sp[t] - sum;
    int4 ov;
    ov.x = excl; ov.y = excl + c.x; ov.z = ov.y + c.y; ov.w = ov.z + c.z;
    *(int4*)(g_cur + base) = ov;
    if (t == 255) g_bsum[b] = sp[255];
}
// scan phase 2: exclusive scan of the 64 block sums
__global__ void k_scan2() {
    __shared__ int sp[64];
    int t = threadIdx.x;
    int v = g_bsum[t];
    sp[t] = v;
    __syncthreads();
    for (int o = 1; o < 64; o <<= 1) {
        int u = (t >= o) ? sp[t - o] : 0;
        __syncthreads();
        sp[t] += u;
        __syncthreads();
    }
    g_bsum[t] = sp[t] - v;
}
// scan phase 3: add block offsets
__global__ __launch_bounds__(256) void k_scan3() {
    int t = threadIdx.x, b = blockIdx.x;
    int off = g_bsum[b];
    int base = b * 1024 + t * 4;
    int4 v = *(const int4*)(g_cur + base);
    v.x += off; v.y += off; v.z += off; v.w += off;
    *(int4*)(g_cur + base) = v;
}
__global__ void k_scatter(const int* __restrict__ labels) {
    int i = blockIdx.x * 256 + threadIdx.x;
    if (i < N_PTS) {
        int l = labels[i];
        int pos = atomicAdd(&g_cur[l], 1);
        g_sidx[pos] = i;
        g_slbl[pos] = l;
    }
}

// ---------------------------------------------------------------------------
// Kernel 1: per-point MLPs over 4 CONSECUTIVE SORTED points per thread.
// R4 compute structure (two f32x2 point-pairs, LDS.128 j-pair weights).
// Scatter: red4 merged across equal adjacent labels (sorted => prefix chain).
// ---------------------------------------------------------------------------
__global__ __launch_bounds__(128) void k_point(
    const float* __restrict__ pf,
    const float* __restrict__ cc, const float* __restrict__ pts,
    const float* __restrict__ we0, const float* __restrict__ be0,
    const float* __restrict__ we1, const float* __restrict__ be1,
    const float* __restrict__ we2, const float* __restrict__ be2,
    const float* __restrict__ we3, const float* __restrict__ be3,
    const float* __restrict__ wa0, const float* __restrict__ ba0,
    const float* __restrict__ wa1, const float* __restrict__ ba1)
{
    __shared__ __align__(16) uint64_t s[3730];
    uint64_t* sWE0 = s + 0;     // 88
    uint64_t* sBE0 = s + 88;    // 8
    uint64_t* sWE1 = s + 96;    // 128
    uint64_t* sBE1 = s + 224;   // 16
    uint64_t* sWE2 = s + 240;   // 512
    uint64_t* sBE2 = s + 752;   // 32
    uint64_t* sWE3 = s + 784;   // 2048
    uint64_t* sBE3 = s + 2832;  // 64
    uint64_t* sWA0 = s + 2896;  // 704
    uint64_t* sBA0 = s + 3600;  // 64
    uint64_t* sWA1 = s + 3664;  // 64
    uint64_t* sBA1 = s + 3728;  // 1

    const int t = threadIdx.x;
    {
        #define DUP(dst, src, n) for (int i = t; i < (n); i += 128) { float v = (src)[i]; (dst)[i] = pack2(v, v); }
        DUP(sWE0, we0, 88)   DUP(sBE0, be0, 8)
        DUP(sWE1, we1, 128)  DUP(sBE1, be1, 16)
        DUP(sWE2, we2, 512)  DUP(sBE2, be2, 32)
        DUP(sWE3, we3, 2048) DUP(sBE3, be3, 64)
        DUP(sWA0, wa0, 704)  DUP(sBA0, ba0, 64)
        DUP(sWA1, wa1, 64)   DUP(sBA1, ba1, 1)
        #undef DUP
    }
    __syncthreads();

    const int gid = blockIdx.x * 128 + t;
    if (gid >= N_THREADS_PT) return;
    const int pos0 = gid * 4;

    const int4 sidx = *(const int4*)(g_sidx + pos0);
    const int4 slbl = *(const int4*)(g_slbl + pos0);
    const int idx[4] = {sidx.x, sidx.y, sidx.z, sidx.w};
    const int lbl[4] = {slbl.x, slbl.y, slbl.z, slbl.w};

    // pair q packs points (2q, 2q+1)
    uint64_t x2[2][11];
#pragma unroll
    for (int q = 0; q < 2; q++) {
        int ia = idx[2 * q], ib = idx[2 * q + 1];
        const float4* pa = (const float4*)(pf + (size_t)ia * 8);
        const float4* pb = (const float4*)(pf + (size_t)ib * 8);
        float4 a0 = pa[0], a1 = pa[1], b0 = pb[0], b1 = pb[1];
        x2[q][0] = pack2(a0.x, b0.x); x2[q][1] = pack2(a0.y, b0.y);
        x2[q][2] = pack2(a0.z, b0.z); x2[q][3] = pack2(a0.w, b0.w);
        x2[q][4] = pack2(a1.x, b1.x); x2[q][5] = pack2(a1.y, b1.y);
        x2[q][6] = pack2(a1.z, b1.z); x2[q][7] = pack2(a1.w, b1.w);
        int la = lbl[2 * q], lb = lbl[2 * q + 1];
#pragma unroll
        for (int k = 0; k < 3; k++)
            x2[q][8 + k] = pack2(cc[(size_t)la * 3 + k] - pts[(size_t)ia * 3 + k],
                                 cc[(size_t)lb * 3 + k] - pts[(size_t)ib * 3 + k]);
    }

    // ----- attention: j-pairs -----
    uint64_t aa0 = sBA1[0], aa1 = aa0;
#pragma unroll 2
    for (int j = 0; j < 64; j += 2) {
        ulonglong2 b = *(const ulonglong2*)&sBA0[j];
        uint64_t c00 = b.x, c01 = b.y, c10 = b.x, c11 = b.y;
#pragma unroll
        for (int k = 0; k < 11; k++) {
            ulonglong2 w = *(const ulonglong2*)&sWA0[k * 64 + j];
            c00 = fma2(x2[0][k], w.x, c00); c01 = fma2(x2[0][k], w.y, c01);
            c10 = fma2(x2[1][k], w.x, c10); c11 = fma2(x2[1][k], w.y, c11);
        }
        ulonglong2 w1 = *(const ulonglong2*)&sWA1[j];
        aa0 = fma2(relu2(c00), w1.x, aa0); aa0 = fma2(relu2(c01), w1.y, aa0);
        aa1 = fma2(relu2(c10), w1.x, aa1); aa1 = fma2(relu2(c11), w1.y, aa1);
    }
    uint64_t a2[2];
    {
        float2 v0 = unpack2(aa0), v1 = unpack2(aa1);
        a2[0] = pack2(1.0f / (1.0f + __expf(-v0.x)), 1.0f / (1.0f + __expf(-v0.y)));
        a2[1] = pack2(1.0f / (1.0f + __expf(-v1.x)), 1.0f / (1.0f + __expf(-v1.y)));
    }

    // ----- edge L0: 11 -> 8 -----
    uint64_t h0[2][8];
#pragma unroll
    for (int j = 0; j < 8; j += 2) {
        ulonglong2 b = *(const ulonglong2*)&sBE0[j];
        uint64_t c00 = b.x, c01 = b.y, c10 = b.x, c11 = b.y;
#pragma unroll
        for (int k = 0; k < 11; k++) {
            ulonglong2 w = *(const ulonglong2*)&sWE0[k * 8 + j];
            c00 = fma2(x2[0][k], w.x, c00); c01 = fma2(x2[0][k], w.y, c01);
            c10 = fma2(x2[1][k], w.x, c10); c11 = fma2(x2[1][k], w.y, c11);
        }
        h0[0][j] = relu2(c00); h0[0][j + 1] = relu2(c01);
        h0[1][j] = relu2(c10); h0[1][j + 1] = relu2(c11);
    }

    // ----- edge L1: 8 -> 16 -----
    uint64_t h1[2][16];
#pragma unroll
    for (int j = 0; j < 16; j += 2) {
        ulonglong2 b = *(const ulonglong2*)&sBE1[j];
        uint64_t c00 = b.x, c01 = b.y, c10 = b.x, c11 = b.y;
#pragma unroll
        for (int k = 0; k < 8; k++) {
            ulonglong2 w = *(const ulonglong2*)&sWE1[k * 16 + j];
            c00 = fma2(h0[0][k], w.x, c00); c01 = fma2(h0[0][k], w.y, c01);
            c10 = fma2(h0[1][k], w.x, c10); c11 = fma2(h0[1][k], w.y, c11);
        }
        h1[0][j] = relu2(c00); h1[0][j + 1] = relu2(c01);
        h1[1][j] = relu2(c10); h1[1][j + 1] = relu2(c11);
    }

    // ----- edge L2: 16 -> 32 -----
    uint64_t h2[2][32];
#pragma unroll 2
    for (int j = 0; j < 32; j += 2) {
        ulonglong2 b = *(const ulonglong2*)&sBE2[j];
        uint64_t c00 = b.x, c01 = b.y, c10 = b.x, c11 = b.y;
#pragma unroll
        for (int k = 0; k < 16; k++) {
            ulonglong2 w = *(const ulonglong2*)&sWE2[k * 32 + j];
            c00 = fma2(h1[0][k], w.x, c00); c01 = fma2(h1[0][k], w.y, c01);
            c10 = fma2(h1[1][k], w.x, c10); c11 = fma2(h1[1][k], w.y, c11);
        }
        h2[0][j] = relu2(c00); h2[0][j + 1] = relu2(c01);
        h2[1][j] = relu2(c10); h2[1][j + 1] = relu2(c11);
    }

    // ----- edge L3: 32 -> 64, streamed; label-merged vector scatter -----
    const bool e01 = (lbl[0] == lbl[1]);
    const bool e12 = (lbl[1] == lbl[2]);
    const bool e23 = (lbl[2] == lbl[3]);

#pragma unroll 1
    for (int j4 = 0; j4 < 16; j4++) {
        float r[4][4];
#pragma unroll
        for (int jj = 0; jj < 4; jj += 2) {
            int j = j4 * 4 + jj;
            ulonglong2 b = *(const ulonglong2*)&sBE3[j];
            uint64_t c00 = b.x, c01 = b.y, c10 = b.x, c11 = b.y;
#pragma unroll
            for (int k = 0; k < 32; k++) {
                ulonglong2 w = *(const ulonglong2*)&sWE3[k * 64 + j];
                c00 = fma2(h2[0][k], w.x, c00); c01 = fma2(h2[0][k], w.y, c01);
                c10 = fma2(h2[1][k], w.x, c10); c11 = fma2(h2[1][k], w.y, c11);
            }
            c00 = mul2(relu2(c00), a2[0]); c01 = mul2(relu2(c01), a2[0]);
            c10 = mul2(relu2(c10), a2[1]); c11 = mul2(relu2(c11), a2[1]);
            float2 f00 = unpack2(c00), f01 = unpack2(c01);
            float2 f10 = unpack2(c10), f11 = unpack2(c11);
            r[0][jj] = f00.x; r[0][jj + 1] = f01.x;
            r[1][jj] = f00.y; r[1][jj + 1] = f01.y;
            r[2][jj] = f10.x; r[2][jj + 1] = f11.x;
            r[3][jj] = f10.y; r[3][jj + 1] = f11.y;
        }

        // merge adjacent equal labels (sorted) before the atomic
        float s0 = r[0][0], s1 = r[0][1], s2 = r[0][2], s3 = r[0][3];
        const int off = j4 * 4;
#pragma unroll
        for (int p = 1; p < 4; p++) {
            bool eq = (p == 1) ? e01 : ((p == 2) ? e12 : e23);
            if (eq) {
                s0 += r[p][0]; s1 += r[p][1]; s2 += r[p][2]; s3 += r[p][3];
            } else {
                red4(g_agg + (size_t)lbl[p - 1] * 64 + off, s0, s1, s2, s3);
                s0 = r[p][0]; s1 = r[p][1]; s2 = r[p][2]; s3 = r[p][3];
            }
        }
        red4(g_agg + (size_t)lbl[3] * 64 + off, s0, s1, s2, s3);
    }
}

// ---------------------------------------------------------------------------
// Kernel 2: g_mid = relu(g_agg @ wo0 + bo0). 16 clusters/block.
// Output blocked [c/32][k][c%32].
// ---------------------------------------------------------------------------
__global__ __launch_bounds__(256) void k_mid(
    const float* __restrict__ wo0, const float* __restrict__ bo0)
{
    __shared__ float sw[64 * 128];
    __shared__ float sb[128];
    __shared__ __align__(16) float saggT[64 * 16];

    const int t  = threadIdx.x;
    const int cb = blockIdx.x * 16;

    for (int i = t; i < 8192; i += 256) sw[i] = wo0[i];
    if (t < 128) sb[t] = bo0[t];
    {
        int c  = t >> 4;
        int k4 = t & 15;
        float4 v = ((const float4*)g_agg)[(size_t)(cb + c) * 16 + k4];
        saggT[(k4 * 4 + 0) * 16 + c] = v.x;
        saggT[(k4 * 4 + 1) * 16 + c] = v.y;
        saggT[(k4 * 4 + 2) * 16 + c] = v.z;
        saggT[(k4 * 4 + 3) * 16 + c] = v.w;
    }
    __syncthreads();

    const int j    = t & 127;
    const int half = t >> 7;

    uint64_t acc[4];
    {
        float b = sb[j];
#pragma unroll
        for (int p = 0; p < 4; p++) acc[p] = pack2(b, b);
    }

#pragma unroll 4
    for (int k = 0; k < 64; k++) {
        float w = sw[k * 128 + j];
        uint64_t w2 = pack2(w, w);
        const uint64_t* row = (const uint64_t*)(saggT + k * 16) + half * 4;
        ulonglong2 m0 = *(const ulonglong2*)(row);
        ulonglong2 m1 = *(const ulonglong2*)(row + 2);
        acc[0] = fma2(m0.x, w2, acc[0]);
        acc[1] = fma2(m0.y, w2, acc[1]);
        acc[2] = fma2(m1.x, w2, acc[2]);
        acc[3] = fma2(m1.y, w2, acc[3]);
    }

    const int group = blockIdx.x >> 1;
    const int lane0 = (blockIdx.x & 1) * 16 + half * 8;
    float* dst = g_mid + (size_t)group * 4096 + (size_t)j * 32 + lane0;
#pragma unroll
    for (int p = 0; p < 4; p++) {
        float2 f = unpack2(acc[p]);
        f.x = fmaxf(f.x, 0.0f); f.y = fmaxf(f.y, 0.0f);
        ((float2*)dst)[p] = f;
    }
}

// ---------------------------------------------------------------------------
// Kernel 3: out = relu(g_mid @ wo1 + bo1). 32 clusters/block, 128 threads.
// ---------------------------------------------------------------------------
__global__ __launch_bounds__(128) void k_out(
    const float* __restrict__ wo1, const float* __restrict__ bo1,
    float* __restrict__ out)
{
    __shared__ __align__(16) uint64_t smid[128 * 16];

    const int t    = threadIdx.x;
    const int cg   = t & 63;
    const int half = t >> 6;
    const int grp  = blockIdx.x;

    const uint64_t* gm = (const uint64_t*)(g_mid + (size_t)grp * 4096);
    for (int i = t; i < 2048; i += 128) smid[i] = gm[i];
    __syncthreads();

    uint64_t acc[4][8];
    {
        float4 b = ((const float4*)bo1)[cg];
#pragma unroll
        for (int p = 0; p < 8; p++) {
            acc[0][p] = pack2(b.x, b.x); acc[1][p] = pack2(b.y, b.y);
            acc[2][p] = pack2(b.z, b.z); acc[3][p] = pack2(b.w, b.w);
        }
    }

    const float4* w4p = (const float4*)wo1;
#pragma unroll 4
    for (int k = 0; k < 128; k++) {
        float4 w = w4p[k * 64 + cg];
        uint64_t wd0 = pack2(w.x, w.x), wd1 = pack2(w.y, w.y);
        uint64_t wd2 = pack2(w.z, w.z), wd3 = pack2(w.w, w.w);
        const uint64_t* mrow = smid + k * 16 + half * 8;
        ulonglong2 m0 = *(const ulonglong2*)(mrow);
        ulonglong2 m1 = *(const ulonglong2*)(mrow + 2);
        ulonglong2 m2 = *(const ulonglong2*)(mrow + 4);
        ulonglong2 m3 = *(const ulonglong2*)(mrow + 6);
        uint64_t m[8] = {m0.x, m0.y, m1.x, m1.y, m2.x, m2.y, m3.x, m3.y};
#pragma unroll
        for (int p = 0; p < 8; p++) {
            acc[0][p] = fma2(m[p], wd0, acc[0][p]);
            acc[1][p] = fma2(m[p], wd1, acc[1][p]);
            acc[2][p] = fma2(m[p], wd2, acc[2][p]);
            acc[3][p] = fma2(m[p], wd3, acc[3][p]);
        }
    }

#pragma unroll
    for (int p = 0; p < 8; p++) {
        int pp = half * 8 + p;
        int c0 = grp * 32 + 2 * pp;
        float2 f0 = unpack2(acc[0][p]), f1 = unpack2(acc[1][p]);
        float2 f2 = unpack2(acc[2][p]), f3 = unpack2(acc[3][p]);
        float4 o0 = make_float4(fmaxf(f0.x, 0.f), fmaxf(f1.x, 0.f),
                                fmaxf(f2.x, 0.f), fmaxf(f3.x, 0.f));
        float4 o1 = make_float4(fmaxf(f0.y, 0.f), fmaxf(f1.y, 0.f),
                                fmaxf(f2.y, 0.f), fmaxf(f3.y, 0.f));
        *(float4*)(out + (size_t)c0 * 256 + 4 * cg)       = o0;
        *(float4*)(out + (size_t)(c0 + 1) * 256 + 4 * cg) = o1;
    }
}

// ---------------------------------------------------------------------------
extern "C" void kernel_launch(void* const* d_in, const int* in_sizes, int n_in,
                              void* d_out, int out_size)
{
    const float* pf     = (const float*)d_in[0];
    const int*   labels = (const int*)  d_in[1];
    const float* cc     = (const float*)d_in[2];
    const float* pts    = (const float*)d_in[3];
    const float* we0    = (const float*)d_in[4];
    const float* be0    = (const float*)d_in[5];
    const float* we1    = (const float*)d_in[6];
    const float* be1    = (const float*)d_in[7];
    const float* we2    = (const float*)d_in[8];
    const float* be2    = (const float*)d_in[9];
    const float* we3    = (const float*)d_in[10];
    const float* be3    = (const float*)d_in[11];
    const float* wa0    = (const float*)d_in[12];
    const float* ba0    = (const float*)d_in[13];
    const float* wa1    = (const float*)d_in[14];
    const float* ba1    = (const float*)d_in[15];
    const float* wo0    = (const float*)d_in[16];
    const float* bo0    = (const float*)d_in[17];
    const float* wo1    = (const float*)d_in[18];
    const float* bo1    = (const float*)d_in[19];
    float* out = (float*)d_out;

    k_zero_agg<<<N_CLU * 64 / 4 / 256, 256>>>();
    k_zero_cnt<<<N_CLU / 4 / 256, 256>>>();
    k_hist<<<(N_PTS + 255) / 256, 256>>>(labels);
    k_scan1<<<64, 256>>>();
    k_scan2<<<1, 64>>>();
    k_scan3<<<64, 256>>>();
    k_scatter<<<(N_PTS + 255) / 256, 256>>>(labels);
    k_point<<<(N_THREADS_PT + 127) / 128, 128>>>(pf, cc, pts,
                                                 we0, be0, we1, be1, we2, be2, we3, be3,
                                                 wa0, ba0, wa1, ba1);
    k_mid<<<N_CLU / 16, 256>>>(wo0, bo0);
    k_out<<<N_CLU / 32, 128>>>(wo1, bo1, out);
}